// round 1
// baseline (speedup 1.0000x reference)
#include <cuda_runtime.h>
#include <math.h>

// Problem dims
#define BB 64
#define TT 256
#define ZZ 128
#define HH 512
#define FF 64
#define MROWS (BB*TT)      // 16384
#define G4H   (4*HH)       // 2048
#define LSTM_BLOCKS (HH/4) // 128

// ------------------------------ scratch buffers (static device, no malloc) --
__device__ float d_xk[MROWS * G4H];     // 134 MB  gate pre-activations
__device__ float d_seqA[MROWS * HH];    // 33.5 MB
__device__ float d_seqB[MROWS * HH];    // 33.5 MB
__device__ float d_res[MROWS * HH];     // 33.5 MB
__device__ float d_W0eff[ZZ * G4H];     // folded Wp@K0
__device__ float d_b0eff[G4H];
__device__ float d_hT[HH * BB];         // h state, [hidden][batch]
__device__ unsigned g_arrive;
__device__ unsigned g_gen;

__device__ __forceinline__ float sigf(float x) { return 1.f / (1.f + expf(-x)); }

// ------------------------------ hand-rolled grid barrier ---------------------
__device__ __forceinline__ void grid_barrier() {
    __syncthreads();
    if (threadIdx.x == 0) {
        __threadfence();
        unsigned my = *(volatile unsigned*)&g_gen;
        if (atomicAdd(&g_arrive, 1u) == gridDim.x - 1u) {
            g_arrive = 0u;
            __threadfence();
            atomicAdd(&g_gen, 1u);
        } else {
            while (*(volatile unsigned*)&g_gen == my) {}
        }
        __threadfence();
    }
    __syncthreads();
}

// ------------------------------ bias fold: b0eff = bp@K0 + b0 ----------------
__global__ void bias_fold_kernel(const float* __restrict__ bp,
                                 const float* __restrict__ K0,
                                 const float* __restrict__ b0) {
    int j = blockIdx.x * blockDim.x + threadIdx.x;   // 0..2047
    float s = 0.f;
    for (int k = 0; k < 2 * HH; ++k) s += bp[k] * K0[k * G4H + j];
    d_b0eff[j] = s + b0[j];
}

// ------------------------------ generic SGEMM 64x64x16, 4x4/thread ----------
// AMAP: 0 identity row, 1 z-order (m=(t,b) -> row b*T+t)
// OMAP: 0 identity, 1 (t,b)->(b,t) output rows
// ACT : 0 none, 1 relu, 2 tanh
// ADD2: A := A + A2 (identity-mapped)
// HASB: add bias[n]
template<int AMAP, int ACT, int OMAP, int ADD2, int HASB>
__global__ __launch_bounds__(256)
void sgemm64(const float* __restrict__ A, const float* __restrict__ A2,
             const float* __restrict__ Bm, const float* __restrict__ bias,
             float* __restrict__ C, int M, int N, int K) {
    __shared__ float As[16][64];
    __shared__ float Bs[16][64];
    const int tid = threadIdx.x;
    const int tx = tid & 15, ty = tid >> 4;
    const int n0 = blockIdx.x * 64, m0 = blockIdx.y * 64;

    float acc[4][4];
#pragma unroll
    for (int i = 0; i < 4; ++i)
#pragma unroll
        for (int j = 0; j < 4; ++j) acc[i][j] = 0.f;

    const int arowl = tid >> 2;
    const int kq = (tid & 3) * 4;
    const int krow = tid >> 4;
    const int nq = (tid & 15) * 4;

    for (int k0 = 0; k0 < K; k0 += 16) {
        {   // A tile (store transposed As[k][m])
            int m = m0 + arowl;
            int arow = (AMAP == 1) ? ((m & 63) * TT + (m >> 6)) : m;
            float4 av = *(const float4*)(A + (size_t)arow * K + k0 + kq);
            if (ADD2) {
                float4 a2 = *(const float4*)(A2 + (size_t)m * K + k0 + kq);
                av.x += a2.x; av.y += a2.y; av.z += a2.z; av.w += a2.w;
            }
            As[kq + 0][arowl] = av.x;
            As[kq + 1][arowl] = av.y;
            As[kq + 2][arowl] = av.z;
            As[kq + 3][arowl] = av.w;
        }
        {   // B tile
            float4 bv = *(const float4*)(Bm + (size_t)(k0 + krow) * N + n0 + nq);
            *(float4*)&Bs[krow][nq] = bv;
        }
        __syncthreads();
#pragma unroll
        for (int k = 0; k < 16; ++k) {
            float4 a = *(const float4*)&As[k][ty * 4];
            float4 b = *(const float4*)&Bs[k][tx * 4];
            float ar[4] = {a.x, a.y, a.z, a.w};
            float br[4] = {b.x, b.y, b.z, b.w};
#pragma unroll
            for (int i = 0; i < 4; ++i)
#pragma unroll
                for (int j = 0; j < 4; ++j) acc[i][j] += ar[i] * br[j];
        }
        __syncthreads();
    }

#pragma unroll
    for (int i = 0; i < 4; ++i) {
        int m = m0 + ty * 4 + i;
        size_t ro = (OMAP == 1) ? (size_t)((m & 63) * TT + (m >> 6)) * N
                                : (size_t)m * N;
        float4 v;
        float* vp = (float*)&v;
#pragma unroll
        for (int j = 0; j < 4; ++j) {
            int n = n0 + tx * 4 + j;
            float t = acc[i][j];
            if (HASB) t += bias[n];
            if (ACT == 1) t = fmaxf(t, 0.f);
            if (ACT == 2) t = tanhf(t);
            vp[j] = t;
        }
        *(float4*)(C + ro + n0 + tx * 4) = v;
    }
}

// ------------------------------ LSTM recurrence ------------------------------
// 128 blocks x 512 threads. Block bidx owns hidden units [bidx*4, bidx*4+4)
// and the 16 gate columns {g*512 + cb + u}. R slice cached in SMEM once.
// Per step: gates = xk[t] + h @ R  (split-K(8) per warp, shfl reduce),
// then cell update with c resident in SMEM, h exchanged via L2 (ldcg/stcg).
__global__ __launch_bounds__(512)
void lstm_kernel(const float* __restrict__ xk, const float* __restrict__ R,
                 float* __restrict__ hseq) {
    __shared__ float Rs[HH * 16];   // [k][jl]  32 KB
    __shared__ float gsm[BB * 16];  // gates    4 KB
    __shared__ float csm[BB * 4];   // cell     1 KB

    const int tid = threadIdx.x;
    const int cb = blockIdx.x * 4;

    // load R slice: jl = gate*4+u -> column gate*512 + cb + u
    for (int i = tid; i < HH * 16; i += 512) {
        int k = i >> 4, jl = i & 15;
        int col = (jl >> 2) * HH + cb + (jl & 3);
        Rs[i] = R[k * G4H + col];
    }
    // init h rows we own + cell state
    for (int i = tid; i < 4 * BB; i += 512)
        __stcg(&d_hT[(cb + (i >> 6)) * BB + (i & 63)], 0.f);
    if (tid < 256) csm[tid] = 0.f;
    grid_barrier();

    const int lane = tid & 31;
    const int warp = tid >> 5;       // = bgroup (16 warps, 4 batches each)
    const int s    = lane & 7;       // k-split 8
    const int cg   = lane >> 3;      // col group (4 cols each)
    const int bg   = warp;

    const float4* hT4 = (const float4*)d_hT;           // [k][16] float4
    const float4* rp0 = (const float4*)Rs;             // [k][4]  float4

    for (int t = 0; t < TT; ++t) {
        const float* xkt = xk + (size_t)t * BB * G4H;
        float acc[16];
#pragma unroll
        for (int i = 0; i < 16; ++i) acc[i] = 0.f;

        const float4* hp = hT4 + (size_t)s * 64 * 16 + bg;
        const float4* rp = rp0 + (size_t)s * 64 * 4 + cg;
#pragma unroll 4
        for (int kk = 0; kk < 64; ++kk) {
            float4 hv = __ldcg(hp + kk * 16);
            float4 rv = rp[kk * 4];
            acc[ 0] += hv.x * rv.x; acc[ 1] += hv.x * rv.y;
            acc[ 2] += hv.x * rv.z; acc[ 3] += hv.x * rv.w;
            acc[ 4] += hv.y * rv.x; acc[ 5] += hv.y * rv.y;
            acc[ 6] += hv.y * rv.z; acc[ 7] += hv.y * rv.w;
            acc[ 8] += hv.z * rv.x; acc[ 9] += hv.z * rv.y;
            acc[10] += hv.z * rv.z; acc[11] += hv.z * rv.w;
            acc[12] += hv.w * rv.x; acc[13] += hv.w * rv.y;
            acc[14] += hv.w * rv.z; acc[15] += hv.w * rv.w;
        }
        // reduce the 8 k-split lanes (same cg) down to s==0
#pragma unroll
        for (int i = 0; i < 16; ++i) {
            acc[i] += __shfl_down_sync(0xffffffffu, acc[i], 4, 8);
            acc[i] += __shfl_down_sync(0xffffffffu, acc[i], 2, 8);
            acc[i] += __shfl_down_sync(0xffffffffu, acc[i], 1, 8);
        }
        if (s == 0) {
#pragma unroll
            for (int bi = 0; bi < 4; ++bi)
#pragma unroll
                for (int ci = 0; ci < 4; ++ci) {
                    int b = bg * 4 + bi, jl = cg * 4 + ci;
                    int col = (jl >> 2) * HH + cb + (jl & 3);
                    gsm[b * 16 + jl] = acc[bi * 4 + ci] + __ldg(&xkt[b * G4H + col]);
                }
        }
        __syncthreads();
        if (tid < 256) {
            int b = tid >> 2, u = tid & 3;
            float iv = gsm[b * 16 + u];
            float fv = gsm[b * 16 + 4 + u];
            float gv = gsm[b * 16 + 8 + u];
            float ov = gsm[b * 16 + 12 + u];
            float c = sigf(fv) * csm[tid] + sigf(iv) * tanhf(gv);
            float h = sigf(ov) * tanhf(c);
            csm[tid] = c;
            __stcg(&d_hT[(cb + u) * BB + b], h);
            hseq[((size_t)t * BB + b) * HH + cb + u] = h;
        }
        grid_barrier();   // h visible to all blocks before next step
    }
}

// ------------------------------ LayerNorm ------------------------------------
__global__ __launch_bounds__(128)
void ln_kernel(const float* __restrict__ x, const float* __restrict__ gamma,
               const float* __restrict__ beta, float* __restrict__ y) {
    const int m = blockIdx.x;
    const int tid = threadIdx.x;  // 128
    __shared__ float red[4];
    float4 v = *(const float4*)(x + (size_t)m * HH + tid * 4);

    float s = v.x + v.y + v.z + v.w;
#pragma unroll
    for (int o = 16; o; o >>= 1) s += __shfl_down_sync(0xffffffffu, s, o);
    if ((tid & 31) == 0) red[tid >> 5] = s;
    __syncthreads();
    float mu = (red[0] + red[1] + red[2] + red[3]) * (1.f / HH);
    __syncthreads();

    float dx = v.x - mu, dy = v.y - mu, dz = v.z - mu, dw = v.w - mu;
    float s2 = dx * dx + dy * dy + dz * dz + dw * dw;
#pragma unroll
    for (int o = 16; o; o >>= 1) s2 += __shfl_down_sync(0xffffffffu, s2, o);
    if ((tid & 31) == 0) red[tid >> 5] = s2;
    __syncthreads();
    float var = (red[0] + red[1] + red[2] + red[3]) * (1.f / HH);
    float rs = rsqrtf(var + 1e-3f);

    float4 g = *(const float4*)(gamma + tid * 4);
    float4 b = *(const float4*)(beta + tid * 4);
    float4 o4;
    o4.x = dx * rs * g.x + b.x;
    o4.y = dy * rs * g.y + b.y;
    o4.z = dz * rs * g.z + b.z;
    o4.w = dw * rs * g.w + b.w;
    *(float4*)(y + (size_t)m * HH + tid * 4) = o4;
}

// ------------------------------ launch ---------------------------------------
extern "C" void kernel_launch(void* const* d_in, const int* in_sizes, int n_in,
                              void* d_out, int out_size) {
    const float* z     = (const float*)d_in[0];
    const float* Wp    = (const float*)d_in[1];
    const float* bp    = (const float*)d_in[2];
    const float* Ws    = (const float*)d_in[3];
    const float* bs    = (const float*)d_in[4];
    const float* K0    = (const float*)d_in[5];
    const float* R0    = (const float*)d_in[6];
    const float* b0    = (const float*)d_in[7];
    const float* K1    = (const float*)d_in[8];
    const float* R1    = (const float*)d_in[9];
    const float* b1    = (const float*)d_in[10];
    const float* K2    = (const float*)d_in[11];
    const float* R2    = (const float*)d_in[12];
    const float* b2    = (const float*)d_in[13];
    const float* gamma = (const float*)d_in[14];
    const float* beta  = (const float*)d_in[15];
    const float* W1    = (const float*)d_in[16];
    const float* b1d   = (const float*)d_in[17];
    const float* W2    = (const float*)d_in[18];
    const float* b2d   = (const float*)d_in[19];
    float* out = (float*)d_out;

    float *xk, *seqA, *seqB, *res, *W0eff, *b0eff;
    cudaGetSymbolAddress((void**)&xk,    d_xk);
    cudaGetSymbolAddress((void**)&seqA,  d_seqA);
    cudaGetSymbolAddress((void**)&seqB,  d_seqB);
    cudaGetSymbolAddress((void**)&res,   d_res);
    cudaGetSymbolAddress((void**)&W0eff, d_W0eff);
    cudaGetSymbolAddress((void**)&b0eff, d_b0eff);

    // 1) fold: b0eff = bp@K0 + b0 ; W0eff = Wp@K0
    bias_fold_kernel<<<G4H / 256, 256>>>(bp, K0, b0);
    sgemm64<0,0,0,0,0><<<dim3(G4H/64, ZZ/64), 256>>>(Wp, nullptr, K0, nullptr,
                                                     W0eff, ZZ, G4H, 2*HH);
    // 2) xK0 = z @ W0eff + b0eff   ([t][b] order)
    sgemm64<1,0,0,0,1><<<dim3(G4H/64, MROWS/64), 256>>>(z, nullptr, W0eff, b0eff,
                                                        xk, MROWS, G4H, ZZ);
    // 3) LSTM 0 -> seqA
    lstm_kernel<<<LSTM_BLOCKS, 512>>>(xk, R0, seqA);
    // 4) residual = z @ Ws + bs   ([t][b] order)
    sgemm64<1,0,0,0,1><<<dim3(HH/64, MROWS/64), 256>>>(z, nullptr, Ws, bs,
                                                       res, MROWS, HH, ZZ);
    // 5) xK1 = seqA @ K1 + b1
    sgemm64<0,0,0,0,1><<<dim3(G4H/64, MROWS/64), 256>>>(seqA, nullptr, K1, b1,
                                                        xk, MROWS, G4H, HH);
    // 6) LSTM 1 -> seqB
    lstm_kernel<<<LSTM_BLOCKS, 512>>>(xk, R1, seqB);
    // 7) xK2 = (seqB + res) @ K2 + b2
    sgemm64<0,0,0,1,1><<<dim3(G4H/64, MROWS/64), 256>>>(seqB, res, K2, b2,
                                                        xk, MROWS, G4H, HH);
    // 8) LSTM 2 -> seqA
    lstm_kernel<<<LSTM_BLOCKS, 512>>>(xk, R2, seqA);
    // 9) LayerNorm: seqA -> seqB
    ln_kernel<<<MROWS, 128>>>(seqA, gamma, beta, seqB);
    // 10) y1 = relu(seqB @ W1 + b1d) -> seqA
    sgemm64<0,1,0,0,1><<<dim3(HH/64, MROWS/64), 256>>>(seqB, nullptr, W1, b1d,
                                                       seqA, MROWS, HH, HH);
    // 11) out = tanh(seqA @ W2 + b2d) -> d_out  ([b][t] order)
    sgemm64<0,2,1,0,1><<<dim3(FF/64, MROWS/64), 256>>>(seqA, nullptr, W2, b2d,
                                                       out, MROWS, FF, HH);
}